// round 3
// baseline (speedup 1.0000x reference)
#include <cuda_runtime.h>
#include <math.h>

#define NB 2
#define TT 16
#define NNODES 10000
#define IND 128
#define HIDD 256
#define OUTD 128
#define NE 160000
#define G3 (3*HIDD)   /* 768 */

// ---------------- static scratch (no runtime allocation) ----------------
__device__ float g_dinv[NNODES];
__device__ int   g_cnt[NNODES];
__device__ int   g_rowptr[NNODES + 1];
__device__ int   g_cursor[NNODES];
__device__ int   g_csr_src[NE];
__device__ float g_csr_w[NE];
__device__ float g_xagg[(size_t)NB * TT * NNODES * IND];   // 164 MB
__device__ float g_h[(size_t)NB * NNODES * HIDD];
__device__ float g_hagg[(size_t)NB * NNODES * HIDD];
__device__ float g_Gx[(size_t)NB * NNODES * G3];
__device__ float g_Gh[(size_t)NB * NNODES * G3];
__device__ float g_Wx[IND * G3];
__device__ float g_Wh[HIDD * G3];

// ---------------- graph preprocessing ----------------
__global__ void k_reset() {
    int i = blockIdx.x * blockDim.x + threadIdx.x;
    if (i < NNODES) { g_cnt[i] = 0; g_cursor[i] = 0; }
}

__global__ void k_count(const int* __restrict__ dst) {
    int e = blockIdx.x * blockDim.x + threadIdx.x;
    if (e < NE) atomicAdd(&g_cnt[dst[e]], 1);
}

__global__ void k_dinv() {
    int i = blockIdx.x * blockDim.x + threadIdx.x;
    if (i < NNODES) g_dinv[i] = rsqrtf((float)g_cnt[i] + 1.0f);  // +1 self loop
}

// single-block exclusive scan of g_cnt -> g_rowptr
__global__ void k_scan() {
    __shared__ int sh[1024];
    __shared__ int carry;
    if (threadIdx.x == 0) { carry = 0; g_rowptr[0] = 0; }
    __syncthreads();
    for (int base = 0; base < NNODES; base += 1024) {
        int i = base + threadIdx.x;
        int v = (i < NNODES) ? g_cnt[i] : 0;
        sh[threadIdx.x] = v;
        __syncthreads();
        for (int off = 1; off < 1024; off <<= 1) {
            int t = (threadIdx.x >= off) ? sh[threadIdx.x - off] : 0;
            __syncthreads();
            sh[threadIdx.x] += t;
            __syncthreads();
        }
        if (i < NNODES) g_rowptr[i + 1] = carry + sh[threadIdx.x];
        __syncthreads();
        if (threadIdx.x == 0) carry += sh[1023];
        __syncthreads();
    }
}

__global__ void k_scatter(const int* __restrict__ src, const int* __restrict__ dst) {
    int e = blockIdx.x * blockDim.x + threadIdx.x;
    if (e >= NE) return;
    int s = src[e], d = dst[e];
    int pos = atomicAdd(&g_cursor[d], 1);
    int slot = g_rowptr[d] + pos;
    g_csr_src[slot] = s;
    g_csr_w[slot] = g_dinv[s] * g_dinv[d];
}

__global__ void k_concat(const float* __restrict__ Wr, const float* __restrict__ Wz,
                         const float* __restrict__ Wn, float* __restrict__ outw, int K) {
    int idx = blockIdx.x * blockDim.x + threadIdx.x;
    if (idx >= K * G3) return;
    int k = idx / G3, c = idx % G3;
    int g = c >> 8, j = c & 255;
    const float* W = (g == 0) ? Wr : ((g == 1) ? Wz : Wn);
    outw[idx] = W[k * HIDD + j];
}

__global__ void k_zero_h() {
    size_t i = (size_t)blockIdx.x * blockDim.x + threadIdx.x;
    if (i < (size_t)NB * NNODES * HIDD) g_h[i] = 0.0f;
}

// ---------------- gather-based normalized-adjacency aggregation ----------------
// grid: (NNODES, nBatch); block: D threads (feature dim). v/out layout: [batch][N][D].
__global__ void k_agg(const float* __restrict__ v, float* __restrict__ outp, int D) {
    int i = blockIdx.x;
    int d = threadIdx.x;
    size_t base = (size_t)blockIdx.y * NNODES * D;
    const float* vb = v + base;
    float* ob = outp + base;
    float di = g_dinv[i];
    float acc = di * di * vb[(size_t)i * D + d];
    int s1 = g_rowptr[i + 1];
    for (int s = g_rowptr[i]; s < s1; s++) {
        acc += g_csr_w[s] * vb[(size_t)g_csr_src[s] * D + d];
    }
    ob[(size_t)i * D + d] = acc;
}

// ---------------- fp32 tiled GEMM: C[b] = A[b] @ Bm (+bias) ----------------
// A: M x K row-major (lda=K), Bm: K x N row-major, C: M x N (ldc=N).
// Requires N % 64 == 0, K % 16 == 0. Grid: (N/64, ceil(M/64), batch).
#define BM 64
#define BN 64
#define BK 16
__global__ void __launch_bounds__(256)
k_sgemm(const float* __restrict__ A, const float* __restrict__ Bm, float* __restrict__ C,
        int M, int K, int N, long sA, long sC, const float* __restrict__ bias) {
    A += (long)blockIdx.z * sA;
    C += (long)blockIdx.z * sC;
    __shared__ float As[BK][BM + 4];
    __shared__ float Bs[BK][BN];
    int tid = threadIdx.x;
    int tx = tid & 15, ty = tid >> 4;
    int rowBase = blockIdx.y * BM;
    int colBase = blockIdx.x * BN;
    float acc[4][4] = {};
    int ar = tid >> 2, ac = (tid & 3) * 4;
    int br = tid >> 4, bc = (tid & 15) * 4;
    for (int k0 = 0; k0 < K; k0 += BK) {
        float4 av = make_float4(0.f, 0.f, 0.f, 0.f);
        int arow = rowBase + ar;
        if (arow < M) av = *reinterpret_cast<const float4*>(A + (long)arow * K + k0 + ac);
        As[ac + 0][ar] = av.x; As[ac + 1][ar] = av.y;
        As[ac + 2][ar] = av.z; As[ac + 3][ar] = av.w;
        float4 bv = *reinterpret_cast<const float4*>(Bm + (long)(k0 + br) * N + colBase + bc);
        *reinterpret_cast<float4*>(&Bs[br][bc]) = bv;
        __syncthreads();
#pragma unroll
        for (int kk = 0; kk < BK; kk++) {
            float4 a4 = *reinterpret_cast<const float4*>(&As[kk][ty * 4]);
            float4 b4 = *reinterpret_cast<const float4*>(&Bs[kk][tx * 4]);
            float a[4] = {a4.x, a4.y, a4.z, a4.w};
            float b[4] = {b4.x, b4.y, b4.z, b4.w};
#pragma unroll
            for (int i = 0; i < 4; i++)
#pragma unroll
                for (int j = 0; j < 4; j++) acc[i][j] += a[i] * b[j];
        }
        __syncthreads();
    }
    int col = colBase + tx * 4;
    float4 badd = make_float4(0.f, 0.f, 0.f, 0.f);
    if (bias) badd = *reinterpret_cast<const float4*>(bias + col);
#pragma unroll
    for (int i = 0; i < 4; i++) {
        int row = rowBase + ty * 4 + i;
        if (row >= M) continue;
        float4 o;
        o.x = acc[i][0] + badd.x;
        o.y = acc[i][1] + badd.y;
        o.z = acc[i][2] + badd.z;
        o.w = acc[i][3] + badd.w;
        *reinterpret_cast<float4*>(C + (long)row * N + col) = o;
    }
}

// ---------------- GRU elementwise update ----------------
__global__ void k_gru(const float* __restrict__ bxr, const float* __restrict__ bhr,
                      const float* __restrict__ bxz, const float* __restrict__ bhz,
                      const float* __restrict__ bxn, const float* __restrict__ bhn) {
    size_t idx = (size_t)blockIdx.x * blockDim.x + threadIdx.x;
    const size_t total = (size_t)NB * NNODES * HIDD;
    if (idx >= total) return;
    int j = (int)(idx & (HIDD - 1));
    size_t row = idx >> 8;  // HIDD = 256
    size_t g = row * G3;
    float r = 1.0f / (1.0f + expf(-(g_Gx[g + j] + bxr[j] + g_Gh[g + j] + bhr[j])));
    float z = 1.0f / (1.0f + expf(-(g_Gx[g + HIDD + j] + bxz[j] + g_Gh[g + HIDD + j] + bhz[j])));
    float n = tanhf(g_Gx[g + 2 * HIDD + j] + bxn[j] + r * (g_Gh[g + 2 * HIDD + j] + bhn[j]));
    float hv = g_h[idx];
    g_h[idx] = (1.0f - z) * hv + z * n;
}

// ---------------- launch ----------------
extern "C" void kernel_launch(void* const* d_in, const int* in_sizes, int n_in,
                              void* d_out, int out_size) {
    const float* x    = (const float*)d_in[0];
    const int*   ei   = (const int*)d_in[1];
    const float* W_xr = (const float*)d_in[2];  const float* b_xr = (const float*)d_in[3];
    const float* W_hr = (const float*)d_in[4];  const float* b_hr = (const float*)d_in[5];
    const float* W_xz = (const float*)d_in[6];  const float* b_xz = (const float*)d_in[7];
    const float* W_hz = (const float*)d_in[8];  const float* b_hz = (const float*)d_in[9];
    const float* W_xn = (const float*)d_in[10]; const float* b_xn = (const float*)d_in[11];
    const float* W_hn = (const float*)d_in[12]; const float* b_hn = (const float*)d_in[13];
    const float* W_fc = (const float*)d_in[14]; const float* b_fc = (const float*)d_in[15];
    float* outp = (float*)d_out;
    const int* src = ei;
    const int* dst = ei + NE;

    float *p_xagg, *p_h, *p_hagg, *p_Gx, *p_Gh, *p_Wx, *p_Wh;
    cudaGetSymbolAddress((void**)&p_xagg, g_xagg);
    cudaGetSymbolAddress((void**)&p_h,    g_h);
    cudaGetSymbolAddress((void**)&p_hagg, g_hagg);
    cudaGetSymbolAddress((void**)&p_Gx,   g_Gx);
    cudaGetSymbolAddress((void**)&p_Gh,   g_Gh);
    cudaGetSymbolAddress((void**)&p_Wx,   g_Wx);
    cudaGetSymbolAddress((void**)&p_Wh,   g_Wh);

    // graph preprocessing (per call; cheap)
    k_reset<<<(NNODES + 255) / 256, 256>>>();
    k_count<<<(NE + 255) / 256, 256>>>(dst);
    k_dinv<<<(NNODES + 255) / 256, 256>>>();
    k_scan<<<1, 1024>>>();
    k_scatter<<<(NE + 255) / 256, 256>>>(src, dst);
    k_concat<<<(IND * G3 + 255) / 256, 256>>>(W_xr, W_xz, W_xn, p_Wx, IND);
    k_concat<<<(HIDD * G3 + 255) / 256, 256>>>(W_hr, W_hz, W_hn, p_Wh, HIDD);
    k_zero_h<<<((size_t)NB * NNODES * HIDD + 255) / 256, 256>>>();

    // x aggregation for all (b,t) slices at once
    k_agg<<<dim3(NNODES, NB * TT), IND>>>(x, p_xagg, IND);

    const int MB = (NNODES + BM - 1) / BM;  // 157
    for (int t = 0; t < TT; t++) {
        // h aggregation
        k_agg<<<dim3(NNODES, NB), HIDD>>>(p_h, p_hagg, HIDD);
        // Gx = xagg_t @ [Wxr|Wxz|Wxn]
        k_sgemm<<<dim3(G3 / BN, MB, NB), 256>>>(
            p_xagg + (size_t)t * NNODES * IND, p_Wx, p_Gx,
            NNODES, IND, G3, (long)TT * NNODES * IND, (long)NNODES * G3, nullptr);
        // Gh = hagg @ [Whr|Whz|Whn]
        k_sgemm<<<dim3(G3 / BN, MB, NB), 256>>>(
            p_hagg, p_Wh, p_Gh,
            NNODES, HIDD, G3, (long)NNODES * HIDD, (long)NNODES * G3, nullptr);
        // GRU update (in-place on h)
        k_gru<<<((size_t)NB * NNODES * HIDD + 255) / 256, 256>>>(b_xr, b_hr, b_xz, b_hz, b_xn, b_hn);
        // out_t = h @ W_fc + b_fc
        k_sgemm<<<dim3(OUTD / BN, MB, NB), 256>>>(
            p_h, W_fc, outp + (size_t)t * NNODES * OUTD,
            NNODES, HIDD, OUTD, (long)NNODES * HIDD, (long)TT * NNODES * OUTD, b_fc);
    }
}

// round 9
// speedup vs baseline: 1.2183x; 1.2183x over previous
#include <cuda_runtime.h>
#include <cuda_bf16.h>
#include <cstdint>
#include <math.h>

#define NB 2
#define TT 16
#define NNODES 10000
#define IND 128
#define HIDD 256
#define OUTD 128
#define NE 160000
#define G3 768
#define MROWS (NB*NNODES)                 /* 20000 */
#define MX ((size_t)NB*TT*NNODES)         /* 640000 */

// ---------------- static scratch ----------------
__device__ float g_dinv[NNODES];
__device__ int   g_cnt[NNODES];
__device__ int   g_rowptr[NNODES + 1];
__device__ int   g_cursor[NNODES];
__device__ int   g_csr_src[NE];
__device__ float g_csr_w[NE];
__device__ float g_h[(size_t)MROWS * HIDD];
__device__ __nv_bfloat16 g_hh[(size_t)MROWS * HIDD], g_hl[(size_t)MROWS * HIDD];
__device__ __nv_bfloat16 g_agh[(size_t)MROWS * HIDD], g_agl[(size_t)MROWS * HIDD];
__device__ __nv_bfloat16 g_xh[MX * IND], g_xl[MX * IND];
__device__ float g_Gx[MX * G3];
__device__ float g_Gh[(size_t)MROWS * G3];
__device__ __nv_bfloat16 g_Wxh[G3 * IND],  g_Wxl[G3 * IND];
__device__ __nv_bfloat16 g_Whh[G3 * HIDD], g_Whl[G3 * HIDD];
__device__ __nv_bfloat16 g_Wfh[OUTD * HIDD], g_Wfl[OUTD * HIDD];

// ---------------- helpers ----------------
static __device__ __forceinline__ uint32_t s2u(const void* p) {
    uint32_t a;
    asm("{ .reg .u64 t; cvta.to.shared.u64 t, %1; cvt.u32.u64 %0, t; }" : "=r"(a) : "l"(p));
    return a;
}

static __device__ __forceinline__ void ldsm4(uint32_t* d, uint32_t addr) {
    asm volatile("ldmatrix.sync.aligned.m8n8.x4.shared.b16 {%0,%1,%2,%3}, [%4];"
                 : "=r"(d[0]), "=r"(d[1]), "=r"(d[2]), "=r"(d[3]) : "r"(addr));
}

static __device__ __forceinline__ void mma16816(float* c, const uint32_t* a, const uint32_t* b) {
    asm volatile(
        "mma.sync.aligned.m16n8k16.row.col.f32.bf16.bf16.f32 "
        "{%0,%1,%2,%3}, {%4,%5,%6,%7}, {%8,%9}, {%0,%1,%2,%3};"
        : "+f"(c[0]), "+f"(c[1]), "+f"(c[2]), "+f"(c[3])
        : "r"(a[0]), "r"(a[1]), "r"(a[2]), "r"(a[3]), "r"(b[0]), "r"(b[1]));
}

static __device__ __forceinline__ void split2(float x, __nv_bfloat16* hi, __nv_bfloat16* lo) {
    __nv_bfloat16 h = __float2bfloat16(x);
    *hi = h;
    *lo = __float2bfloat16(x - __bfloat162float(h));
}

// ---------------- graph preprocessing ----------------
__global__ void k_reset() {
    int i = blockIdx.x * blockDim.x + threadIdx.x;
    if (i < NNODES) { g_cnt[i] = 0; g_cursor[i] = 0; }
}
__global__ void k_count(const int* __restrict__ dst) {
    int e = blockIdx.x * blockDim.x + threadIdx.x;
    if (e < NE) atomicAdd(&g_cnt[dst[e]], 1);
}
__global__ void k_dinv() {
    int i = blockIdx.x * blockDim.x + threadIdx.x;
    if (i < NNODES) g_dinv[i] = rsqrtf((float)g_cnt[i] + 1.0f);
}
__global__ void k_scan() {
    __shared__ int sh[1024];
    __shared__ int carry;
    if (threadIdx.x == 0) { carry = 0; g_rowptr[0] = 0; }
    __syncthreads();
    for (int base = 0; base < NNODES; base += 1024) {
        int i = base + threadIdx.x;
        int v = (i < NNODES) ? g_cnt[i] : 0;
        sh[threadIdx.x] = v;
        __syncthreads();
        for (int off = 1; off < 1024; off <<= 1) {
            int t = (threadIdx.x >= off) ? sh[threadIdx.x - off] : 0;
            __syncthreads();
            sh[threadIdx.x] += t;
            __syncthreads();
        }
        if (i < NNODES) g_rowptr[i + 1] = carry + sh[threadIdx.x];
        __syncthreads();
        if (threadIdx.x == 0) carry += sh[1023];
        __syncthreads();
    }
}
__global__ void k_scatter(const int* __restrict__ src, const int* __restrict__ dst) {
    int e = blockIdx.x * blockDim.x + threadIdx.x;
    if (e >= NE) return;
    int s = src[e], d = dst[e];
    int pos = atomicAdd(&g_cursor[d], 1);
    int slot = g_rowptr[d] + pos;
    g_csr_src[slot] = s;
    g_csr_w[slot] = g_dinv[s] * g_dinv[d];
}
__global__ void k_zero_h() {
    size_t i = (size_t)blockIdx.x * blockDim.x + threadIdx.x;
    if (i < (size_t)MROWS * HIDD) g_h[i] = 0.0f;
}

// ---------------- weight prep: transpose to [N][K] + bf16 hi/lo split ----------------
__global__ void k_prepWx(const float* __restrict__ Wr, const float* __restrict__ Wz,
                         const float* __restrict__ Wn) {
    int idx = blockIdx.x * blockDim.x + threadIdx.x;
    if (idx >= G3 * IND) return;
    int nrow = idx / IND, k = idx % IND;
    int g = nrow >> 8, j = nrow & 255;
    const float* W = (g == 0) ? Wr : ((g == 1) ? Wz : Wn);
    split2(W[k * HIDD + j], &g_Wxh[idx], &g_Wxl[idx]);
}
__global__ void k_prepWh(const float* __restrict__ Wr, const float* __restrict__ Wz,
                         const float* __restrict__ Wn) {
    int idx = blockIdx.x * blockDim.x + threadIdx.x;
    if (idx >= G3 * HIDD) return;
    int nrow = idx / HIDD, k = idx % HIDD;
    int g = nrow >> 8, j = nrow & 255;
    const float* W = (g == 0) ? Wr : ((g == 1) ? Wz : Wn);
    split2(W[k * HIDD + j], &g_Whh[idx], &g_Whl[idx]);
}
__global__ void k_prepWf(const float* __restrict__ Wfc) {
    int idx = blockIdx.x * blockDim.x + threadIdx.x;
    if (idx >= OUTD * HIDD) return;
    int nrow = idx / HIDD, k = idx % HIDD;
    split2(Wfc[k * OUTD + nrow], &g_Wfh[idx], &g_Wfl[idx]);
}

// ---------------- aggregation (gather) with bf16 split output ----------------
__global__ void k_aggx(const float* __restrict__ x) {
    int i = blockIdx.x, d = threadIdx.x;
    int s_in = blockIdx.y;                         // b*TT + t
    const float* vb = x + (size_t)s_in * NNODES * IND;
    float di = g_dinv[i];
    float acc = di * di * vb[(size_t)i * IND + d];
    int s1 = g_rowptr[i + 1];
    for (int s = g_rowptr[i]; s < s1; s++)
        acc += g_csr_w[s] * vb[(size_t)g_csr_src[s] * IND + d];
    int b = s_in / TT, t = s_in % TT;
    size_t o = ((size_t)(t * NB + b) * NNODES + i) * IND + d;
    split2(acc, &g_xh[o], &g_xl[o]);
}
__global__ void k_aggh() {
    int i = blockIdx.x, d = threadIdx.x;
    size_t base = (size_t)blockIdx.y * NNODES * HIDD;
    const float* vb = g_h + base;
    float di = g_dinv[i];
    float acc = di * di * vb[(size_t)i * HIDD + d];
    int s1 = g_rowptr[i + 1];
    for (int s = g_rowptr[i]; s < s1; s++)
        acc += g_csr_w[s] * vb[(size_t)g_csr_src[s] * HIDD + d];
    size_t o = base + (size_t)i * HIDD + d;
    split2(acc, &g_agh[o], &g_agl[o]);
}

// ---------------- bf16x3 GEMM via mma.sync (base ISA, runs on sm_103) ----------------
// C[128x128 tile] = A @ B^T with A,B as hi/lo bf16 planes (A: [M][K], B: [Ntot][K]).
// acc += Ah*Bh + Ah*Bl + Al*Bh (fp32 accumulate). Dropped lo*lo term ~2^-18.
// mode 0: C row-major, ldc = gridDim.x*128. mode 1 (fc): scatter to
// out[((b*TT+t)*NNODES+n)*OUTD + col].
#define LDP 40   /* smem row pitch in bf16 elems (80B) -> conflict-free ldmatrix */

__global__ void __launch_bounds__(256, 2) k_mma(
    const __nv_bfloat16* __restrict__ Ah, const __nv_bfloat16* __restrict__ Al,
    const __nv_bfloat16* __restrict__ Bh, const __nv_bfloat16* __restrict__ Bl,
    float* __restrict__ C, long Mtot, int K,
    const float* __restrict__ bias, int mode, int t)
{
    __shared__ __nv_bfloat16 As_h[128 * LDP], As_l[128 * LDP];
    __shared__ __nv_bfloat16 Bs_h[128 * LDP], Bs_l[128 * LDP];

    const int tid = threadIdx.x;
    const int wid = tid >> 5, lane = tid & 31;
    const int wm = (wid & 1) * 64;      // warp m offset (2 rows of warps)
    const int wn = (wid >> 1) * 32;     // warp n offset (4 cols of warps)
    const long rowA = (long)blockIdx.y * 128;
    const long colB = (long)blockIdx.x * 128;

    const uint32_t sAh = s2u(As_h), sAl = s2u(As_l);
    const uint32_t sBh = s2u(Bs_h), sBl = s2u(Bs_l);

    float acc[4][4][4];
#pragma unroll
    for (int i = 0; i < 4; i++)
#pragma unroll
        for (int j = 0; j < 4; j++)
#pragma unroll
            for (int q = 0; q < 4; q++) acc[i][j][q] = 0.0f;

    const int nch = K >> 5;
    for (int ch = 0; ch < nch; ch++) {
        const int k0 = ch << 5;
        // load 128x32 tiles (hi+lo for A and B) as uint4 chunks
#pragma unroll
        for (int it = 0; it < 2; it++) {
            int idx = tid + it * 256;       // 0..511
            int r = idx >> 2, cs = idx & 3; // row, 16B segment
            long ga = (rowA + r) * (long)K + k0 + cs * 8;
            uint4 vh = make_uint4(0, 0, 0, 0), vl = vh;
            if (rowA + r < Mtot) {
                vh = *(const uint4*)(Ah + ga);
                vl = *(const uint4*)(Al + ga);
            }
            int so = r * LDP + cs * 8;
            *(uint4*)(As_h + so) = vh;
            *(uint4*)(As_l + so) = vl;
            long gb = (colB + r) * (long)K + k0 + cs * 8;
            *(uint4*)(Bs_h + so) = *(const uint4*)(Bh + gb);
            *(uint4*)(Bs_l + so) = *(const uint4*)(Bl + gb);
        }
        __syncthreads();

#pragma unroll
        for (int ks = 0; ks < 2; ks++) {
            const int kb = ks * 16;
            // A fragments: 4 m-tiles of 16, hi and lo
            const int ar = wm + (lane & 15);
            const int ac = kb + (lane >> 4) * 8;
            uint32_t ah[4][4], al[4][4];
#pragma unroll
            for (int mt = 0; mt < 4; mt++) {
                uint32_t off = (uint32_t)(((ar + mt * 16) * LDP + ac) * 2);
                ldsm4(ah[mt], sAh + off);
                ldsm4(al[mt], sAl + off);
            }
            // B fragments: 4 n-tiles of 8, fetched 2 at a time via x4
            const int bn = wn + (lane & 7) + (lane >> 4) * 8;
            const int bk = kb + ((lane >> 3) & 1) * 8;
#pragma unroll
            for (int pn = 0; pn < 2; pn++) {
                uint32_t off = (uint32_t)(((bn + pn * 16) * LDP + bk) * 2);
                uint32_t bh4[4], bl4[4];
                ldsm4(bh4, sBh + off);
                ldsm4(bl4, sBl + off);
#pragma unroll
                for (int mt = 0; mt < 4; mt++) {
#pragma unroll
                    for (int sub = 0; sub < 2; sub++) {
                        int nt = pn * 2 + sub;
                        mma16816(acc[mt][nt], ah[mt], bh4 + sub * 2);
                        mma16816(acc[mt][nt], ah[mt], bl4 + sub * 2);
                        mma16816(acc[mt][nt], al[mt], bh4 + sub * 2);
                    }
                }
            }
        }
        __syncthreads();
    }

    // epilogue
    const int gid = lane >> 2, tig = lane & 3;
    const long ldc = (long)gridDim.x * 128;
#pragma unroll
    for (int mt = 0; mt < 4; mt++) {
#pragma unroll
        for (int half = 0; half < 2; half++) {
            long row = rowA + wm + mt * 16 + gid + half * 8;
            if (row >= Mtot) continue;
            size_t obase;
            if (mode == 0) {
                obase = (size_t)row * ldc;
            } else {
                long b = row / NNODES, n = row - b * NNODES;
                obase = (((size_t)b * TT + t) * NNODES + n) * OUTD;
            }
#pragma unroll
            for (int nt = 0; nt < 4; nt++) {
                long col = colB + wn + nt * 8 + tig * 2;
                float v0 = acc[mt][nt][half * 2 + 0];
                float v1 = acc[mt][nt][half * 2 + 1];
                if (bias) { v0 += bias[col]; v1 += bias[col + 1]; }
                float2 o = make_float2(v0, v1);
                *(float2*)(C + obase + col) = o;
            }
        }
    }
}

// ---------------- GRU elementwise update ----------------
__global__ void k_gru(int t, const float* __restrict__ bxr, const float* __restrict__ bhr,
                      const float* __restrict__ bxz, const float* __restrict__ bhz,
                      const float* __restrict__ bxn, const float* __restrict__ bhn) {
    size_t idx = (size_t)blockIdx.x * blockDim.x + threadIdx.x;
    const size_t total = (size_t)MROWS * HIDD;
    if (idx >= total) return;
    int j = (int)(idx & 255);
    size_t row = idx >> 8;
    const float* gx = g_Gx + ((size_t)t * MROWS + row) * G3;
    const float* gh = g_Gh + row * G3;
    float r = 1.0f / (1.0f + expf(-(gx[j] + bxr[j] + gh[j] + bhr[j])));
    float z = 1.0f / (1.0f + expf(-(gx[256 + j] + bxz[j] + gh[256 + j] + bhz[j])));
    float n = tanhf(gx[512 + j] + bxn[j] + r * (gh[512 + j] + bhn[j]));
    float hv = g_h[idx];
    float hn = (1.0f - z) * hv + z * n;
    g_h[idx] = hn;
    split2(hn, &g_hh[idx], &g_hl[idx]);
}

// ---------------- launch ----------------
extern "C" void kernel_launch(void* const* d_in, const int* in_sizes, int n_in,
                              void* d_out, int out_size) {
    const float* x    = (const float*)d_in[0];
    const int*   ei   = (const int*)d_in[1];
    const float* W_xr = (const float*)d_in[2];  const float* b_xr = (const float*)d_in[3];
    const float* W_hr = (const float*)d_in[4];  const float* b_hr = (const float*)d_in[5];
    const float* W_xz = (const float*)d_in[6];  const float* b_xz = (const float*)d_in[7];
    const float* W_hz = (const float*)d_in[8];  const float* b_hz = (const float*)d_in[9];
    const float* W_xn = (const float*)d_in[10]; const float* b_xn = (const float*)d_in[11];
    const float* W_hn = (const float*)d_in[12]; const float* b_hn = (const float*)d_in[13];
    const float* W_fc = (const float*)d_in[14]; const float* b_fc = (const float*)d_in[15];
    float* outp = (float*)d_out;
    const int* src = ei;
    const int* dst = ei + NE;

    __nv_bfloat16 *p_xh, *p_xl, *p_agh, *p_agl, *p_hh, *p_hl;
    __nv_bfloat16 *p_Wxh, *p_Wxl, *p_Whh, *p_Whl, *p_Wfh, *p_Wfl;
    float *p_Gx, *p_Gh;
    cudaGetSymbolAddress((void**)&p_xh,  g_xh);  cudaGetSymbolAddress((void**)&p_xl,  g_xl);
    cudaGetSymbolAddress((void**)&p_agh, g_agh); cudaGetSymbolAddress((void**)&p_agl, g_agl);
    cudaGetSymbolAddress((void**)&p_hh,  g_hh);  cudaGetSymbolAddress((void**)&p_hl,  g_hl);
    cudaGetSymbolAddress((void**)&p_Wxh, g_Wxh); cudaGetSymbolAddress((void**)&p_Wxl, g_Wxl);
    cudaGetSymbolAddress((void**)&p_Whh, g_Whh); cudaGetSymbolAddress((void**)&p_Whl, g_Whl);
    cudaGetSymbolAddress((void**)&p_Wfh, g_Wfh); cudaGetSymbolAddress((void**)&p_Wfl, g_Wfl);
    cudaGetSymbolAddress((void**)&p_Gx,  g_Gx);  cudaGetSymbolAddress((void**)&p_Gh,  g_Gh);

    // preprocessing
    k_reset<<<(NNODES + 255) / 256, 256>>>();
    k_count<<<(NE + 255) / 256, 256>>>(dst);
    k_dinv<<<(NNODES + 255) / 256, 256>>>();
    k_scan<<<1, 1024>>>();
    k_scatter<<<(NE + 255) / 256, 256>>>(src, dst);
    k_prepWx<<<(G3 * IND + 255) / 256, 256>>>(W_xr, W_xz, W_xn);
    k_prepWh<<<(G3 * HIDD + 255) / 256, 256>>>(W_hr, W_hz, W_hn);
    k_prepWf<<<(OUTD * HIDD + 255) / 256, 256>>>(W_fc);
    k_zero_h<<<((size_t)MROWS * HIDD + 255) / 256, 256>>>();

    // x aggregation for all (b,t), reordered to [t][b][N][IND]
    k_aggx<<<dim3(NNODES, NB * TT), IND>>>(x);

    // Gx for ALL timesteps in one GEMM: [640000 x 128] @ [128 x 768]
    k_mma<<<dim3(G3 / 128, (int)(MX / 128)), 256>>>(
        p_xh, p_xl, p_Wxh, p_Wxl, p_Gx, (long)MX, IND, nullptr, 0, 0);

    const int MT = (MROWS + 127) / 128;  // 157
    for (int t = 0; t < TT; t++) {
        k_aggh<<<dim3(NNODES, NB), HIDD>>>();
        k_mma<<<dim3(G3 / 128, MT), 256>>>(
            p_agh, p_agl, p_Whh, p_Whl, p_Gh, (long)MROWS, HIDD, nullptr, 0, 0);
        k_gru<<<((size_t)MROWS * HIDD + 255) / 256, 256>>>(t, b_xr, b_hr, b_xz, b_hz, b_xn, b_hn);
        k_mma<<<dim3(OUTD / 128, MT), 256>>>(
            p_hh, p_hl, p_Wfh, p_Wfl, outp, (long)MROWS, HIDD, b_fc, 1, t);
    }
}

// round 10
// speedup vs baseline: 1.7480x; 1.4347x over previous
#include <cuda_runtime.h>
#include <cuda_bf16.h>
#include <cstdint>
#include <math.h>

#define NB 2
#define TT 16
#define NNODES 10000
#define IND 128
#define HIDD 256
#define OUTD 128
#define NE 160000
#define G3 768
#define MROWS (NB*NNODES)                 /* 20000 */
#define MX ((size_t)NB*TT*NNODES)         /* 640000 */

// ---------------- static scratch ----------------
__device__ float g_dinv[NNODES];
__device__ int   g_rowptr[NNODES + 1];
__device__ int   g_csr_src[NE];
__device__ float g_csr_w[NE];
__device__ float g_h[(size_t)MROWS * HIDD];
__device__ __nv_bfloat16 g_hh[(size_t)MROWS * HIDD], g_hl[(size_t)MROWS * HIDD];
__device__ __nv_bfloat16 g_agh[(size_t)MROWS * HIDD], g_agl[(size_t)MROWS * HIDD];
__device__ __nv_bfloat16 g_xh[MX * IND], g_xl[MX * IND];
__device__ float g_Gx[MX * G3];
__device__ float g_Gh[(size_t)MROWS * G3];
__device__ __nv_bfloat16 g_Wxh[G3 * IND],  g_Wxl[G3 * IND];
__device__ __nv_bfloat16 g_Whh[G3 * HIDD], g_Whl[G3 * HIDD];
__device__ __nv_bfloat16 g_Wfh[OUTD * HIDD], g_Wfl[OUTD * HIDD];

// ---------------- helpers ----------------
static __device__ __forceinline__ uint32_t s2u(const void* p) {
    uint32_t a;
    asm("{ .reg .u64 t; cvta.to.shared.u64 t, %1; cvt.u32.u64 %0, t; }" : "=r"(a) : "l"(p));
    return a;
}

static __device__ __forceinline__ void ldsm4(uint32_t* d, uint32_t addr) {
    asm volatile("ldmatrix.sync.aligned.m8n8.x4.shared.b16 {%0,%1,%2,%3}, [%4];"
                 : "=r"(d[0]), "=r"(d[1]), "=r"(d[2]), "=r"(d[3]) : "r"(addr));
}

static __device__ __forceinline__ void mma16816(float* c, const uint32_t* a, const uint32_t* b) {
    asm volatile(
        "mma.sync.aligned.m16n8k16.row.col.f32.bf16.bf16.f32 "
        "{%0,%1,%2,%3}, {%4,%5,%6,%7}, {%8,%9}, {%0,%1,%2,%3};"
        : "+f"(c[0]), "+f"(c[1]), "+f"(c[2]), "+f"(c[3])
        : "r"(a[0]), "r"(a[1]), "r"(a[2]), "r"(a[3]), "r"(b[0]), "r"(b[1]));
}

static __device__ __forceinline__ void cpasync16(uint32_t saddr, const void* gaddr, bool pred) {
    int sz = pred ? 16 : 0;
    asm volatile("cp.async.cg.shared.global [%0], [%1], 16, %2;"
                 :: "r"(saddr), "l"(gaddr), "r"(sz) : "memory");
}

static __device__ __forceinline__ void split2(float x, __nv_bfloat16* hi, __nv_bfloat16* lo) {
    __nv_bfloat16 h = __float2bfloat16(x);
    *hi = h;
    *lo = __float2bfloat16(x - __bfloat162float(h));
}

// ---------------- fused prep: weight transpose+split and h zero ----------------
#define PR_WX (G3*IND)                    /* 98304  */
#define PR_WH (G3*HIDD)                   /* 196608 */
#define PR_WF (OUTD*HIDD)                 /* 32768  */
#define PR_H  ((size_t)MROWS*HIDD)        /* 5120000 */
#define PR_TOTAL (PR_WX + PR_WH + PR_WF + PR_H)

__global__ void k_prep(const float* __restrict__ Wxr, const float* __restrict__ Wxz,
                       const float* __restrict__ Wxn, const float* __restrict__ Whr,
                       const float* __restrict__ Whz, const float* __restrict__ Whn,
                       const float* __restrict__ Wfc) {
    size_t idx = (size_t)blockIdx.x * blockDim.x + threadIdx.x;
    if (idx < PR_WX) {
        int i = (int)idx;
        int nrow = i / IND, k = i % IND;
        int g = nrow >> 8, j = nrow & 255;
        const float* W = (g == 0) ? Wxr : ((g == 1) ? Wxz : Wxn);
        split2(W[k * HIDD + j], &g_Wxh[i], &g_Wxl[i]);
        return;
    }
    idx -= PR_WX;
    if (idx < PR_WH) {
        int i = (int)idx;
        int nrow = i / HIDD, k = i % HIDD;
        int g = nrow >> 8, j = nrow & 255;
        const float* W = (g == 0) ? Whr : ((g == 1) ? Whz : Whn);
        split2(W[k * HIDD + j], &g_Whh[i], &g_Whl[i]);
        return;
    }
    idx -= PR_WH;
    if (idx < PR_WF) {
        int i = (int)idx;
        int nrow = i / HIDD, k = i % HIDD;
        split2(Wfc[k * OUTD + nrow], &g_Wfh[i], &g_Wfl[i]);
        return;
    }
    idx -= PR_WF;
    if (idx < PR_H) g_h[idx] = 0.0f;
}

// ---------------- single-block graph build: count + dinv + scan + scatter ----------------
__global__ void __launch_bounds__(1024) k_graph(const int* __restrict__ src,
                                                const int* __restrict__ dst) {
    __shared__ int scnt[NNODES];
    __shared__ int sh[1024];
    __shared__ int carry;
    const int tid = threadIdx.x;

    for (int i = tid; i < NNODES; i += 1024) scnt[i] = 0;
    __syncthreads();
    for (int e = tid; e < NE; e += 1024) atomicAdd(&scnt[dst[e]], 1);
    __syncthreads();
    for (int i = tid; i < NNODES; i += 1024) g_dinv[i] = rsqrtf((float)scnt[i] + 1.0f);
    __syncthreads();

    // exclusive scan of scnt -> g_rowptr
    if (tid == 0) { carry = 0; g_rowptr[0] = 0; }
    __syncthreads();
    for (int base = 0; base < NNODES; base += 1024) {
        int i = base + tid;
        int v = (i < NNODES) ? scnt[i] : 0;
        sh[tid] = v;
        __syncthreads();
        for (int off = 1; off < 1024; off <<= 1) {
            int t = (tid >= off) ? sh[tid - off] : 0;
            __syncthreads();
            sh[tid] += t;
            __syncthreads();
        }
        if (i < NNODES) g_rowptr[i + 1] = carry + sh[tid];
        __syncthreads();
        if (tid == 0) carry += sh[1023];
        __syncthreads();
    }

    // reuse scnt as cursors
    for (int i = tid; i < NNODES; i += 1024) scnt[i] = 0;
    __syncthreads();
    for (int e = tid; e < NE; e += 1024) {
        int s = src[e], d = dst[e];
        int pos = atomicAdd(&scnt[d], 1);
        int slot = g_rowptr[d] + pos;
        g_csr_src[slot] = s;
        g_csr_w[slot] = g_dinv[s] * g_dinv[d];
    }
}

// ---------------- aggregation (gather) with bf16 split output ----------------
__global__ void k_aggx(const float* __restrict__ x) {
    int i = blockIdx.x, d = threadIdx.x;
    int s_in = blockIdx.y;                         // b*TT + t
    const float* vb = x + (size_t)s_in * NNODES * IND;
    float di = g_dinv[i];
    float acc = di * di * vb[(size_t)i * IND + d];
    int s1 = g_rowptr[i + 1];
    for (int s = g_rowptr[i]; s < s1; s++)
        acc += g_csr_w[s] * vb[(size_t)g_csr_src[s] * IND + d];
    int b = s_in / TT, t = s_in % TT;
    size_t o = ((size_t)(t * NB + b) * NNODES + i) * IND + d;
    split2(acc, &g_xh[o], &g_xl[o]);
}
__global__ void k_aggh() {
    int i = blockIdx.x, d = threadIdx.x;
    size_t base = (size_t)blockIdx.y * NNODES * HIDD;
    const float* vb = g_h + base;
    float di = g_dinv[i];
    float acc = di * di * vb[(size_t)i * HIDD + d];
    int s1 = g_rowptr[i + 1];
    for (int s = g_rowptr[i]; s < s1; s++)
        acc += g_csr_w[s] * vb[(size_t)g_csr_src[s] * HIDD + d];
    size_t o = base + (size_t)i * HIDD + d;
    split2(acc, &g_agh[o], &g_agl[o]);
}

// ---------------- bf16x3 GEMM via mma.sync, cp.async 2-stage pipeline ----------------
// C[128x128 tile] = A @ B^T, hi/lo bf16 planes (A: [Mtot][K], B: [Ntot][K]).
// acc += Ah*Bh + Ah*Bl + Al*Bh (fp32 accumulate).
// mode 0: C row-major, ldc = gridDim.x*128. mode 1 (fc): scatter to
// out[((b*TT+t)*NNODES+n)*OUTD + col].
#define LDP 40                       /* smem row pitch, bf16 elems (80B) */
#define TILE_B (128 * LDP * 2)       /* 10240 B per tile */
#define STAGE_B (4 * TILE_B)         /* 40960 B per stage (Ah,Al,Bh,Bl) */
#define SMEMB (2 * STAGE_B)          /* 81920 B */

__global__ void __launch_bounds__(256, 2) k_mma(
    const __nv_bfloat16* __restrict__ Ah, const __nv_bfloat16* __restrict__ Al,
    const __nv_bfloat16* __restrict__ Bh, const __nv_bfloat16* __restrict__ Bl,
    float* __restrict__ C, long Mtot, int K,
    const float* __restrict__ bias, int mode, int t)
{
    extern __shared__ char dsm[];
    const uint32_t sbase = s2u(dsm);

    const int tid = threadIdx.x;
    const int wid = tid >> 5, lane = tid & 31;
    const int wm = (wid & 1) * 64;
    const int wn = (wid >> 1) * 32;
    const long rowA = (long)blockIdx.y * 128;
    const long colB = (long)blockIdx.x * 128;

    // per-thread load geometry (2 iterations of 256 threads cover 512 x 16B per tile)
    const int r0 = tid >> 2, cs0 = (tid & 3);             // it=0
    const int r1 = (tid + 256) >> 2, cs1 = (tid & 3);     // it=1

    float acc[4][4][4];
#pragma unroll
    for (int i = 0; i < 4; i++)
#pragma unroll
        for (int j = 0; j < 4; j++)
#pragma unroll
            for (int q = 0; q < 4; q++) acc[i][j][q] = 0.0f;

    const int nch = K >> 5;

    // ---- load issue for chunk ch into stage st ----
    auto issue = [&](int ch, int st) {
        const int k0 = ch << 5;
        const uint32_t sb = sbase + st * STAGE_B;
#pragma unroll
        for (int it = 0; it < 2; it++) {
            int r = it ? r1 : r0;
            int cs = it ? cs1 : cs0;
            uint32_t so = (uint32_t)((r * LDP + cs * 8) * 2);
            long ra = rowA + r;
            bool va = (ra < Mtot);
            long rca = va ? ra : 0;
            const __nv_bfloat16* pA = Ah + rca * (long)K + k0 + cs * 8;
            const __nv_bfloat16* pAl_ = Al + rca * (long)K + k0 + cs * 8;
            cpasync16(sb + so, pA, va);
            cpasync16(sb + TILE_B + so, pAl_, va);
            long rb = colB + r;
            cpasync16(sb + 2 * TILE_B + so, Bh + rb * (long)K + k0 + cs * 8, true);
            cpasync16(sb + 3 * TILE_B + so, Bl + rb * (long)K + k0 + cs * 8, true);
        }
        asm volatile("cp.async.commit_group;" ::: "memory");
    };

    issue(0, 0);
    int buf = 0;
    for (int ch = 0; ch < nch; ch++) {
        if (ch + 1 < nch) {
            issue(ch + 1, buf ^ 1);
            asm volatile("cp.async.wait_group 1;" ::: "memory");
        } else {
            asm volatile("cp.async.wait_group 0;" ::: "memory");
        }
        __syncthreads();

        const uint32_t sb = sbase + buf * STAGE_B;
        const uint32_t sAh = sb, sAl = sb + TILE_B;
        const uint32_t sBh = sb + 2 * TILE_B, sBl = sb + 3 * TILE_B;

#pragma unroll
        for (int ks = 0; ks < 2; ks++) {
            const int kb = ks * 16;
            const int ar = wm + (lane & 15);
            const int ac = kb + (lane >> 4) * 8;
            uint32_t ah[4][4], al[4][4];
#pragma unroll
            for (int mt = 0; mt < 4; mt++) {
                uint32_t off = (uint32_t)(((ar + mt * 16) * LDP + ac) * 2);
                ldsm4(ah[mt], sAh + off);
                ldsm4(al[mt], sAl + off);
            }
            const int bn = wn + (lane & 7) + (lane >> 4) * 8;
            const int bk = kb + ((lane >> 3) & 1) * 8;
#pragma unroll
            for (int pn = 0; pn < 2; pn++) {
                uint32_t off = (uint32_t)(((bn + pn * 16) * LDP + bk) * 2);
                uint32_t bh4[4], bl4[4];
                ldsm4(bh4, sBh + off);
                ldsm4(bl4, sBl + off);
#pragma unroll
                for (int mt = 0; mt < 4; mt++) {
#pragma unroll
                    for (int sub = 0; sub < 2; sub++) {
                        int nt = pn * 2 + sub;
                        mma16816(acc[mt][nt], ah[mt], bh4 + sub * 2);
                        mma16816(acc[mt][nt], ah[mt], bl4 + sub * 2);
                        mma16816(acc[mt][nt], al[mt], bh4 + sub * 2);
                    }
                }
            }
        }
        __syncthreads();
        buf ^= 1;
    }

    // epilogue
    const int gid = lane >> 2, tig = lane & 3;
    const long ldc = (long)gridDim.x * 128;
#pragma unroll
    for (int mt = 0; mt < 4; mt++) {
#pragma unroll
        for (int half = 0; half < 2; half++) {
            long row = rowA + wm + mt * 16 + gid + half * 8;
            if (row >= Mtot) continue;
            size_t obase;
            if (mode == 0) {
                obase = (size_t)row * ldc;
            } else {
                long b = row / NNODES, n = row - b * NNODES;
                obase = (((size_t)b * TT + t) * NNODES + n) * OUTD;
            }
#pragma unroll
            for (int nt = 0; nt < 4; nt++) {
                long col = colB + wn + nt * 8 + tig * 2;
                float v0 = acc[mt][nt][half * 2 + 0];
                float v1 = acc[mt][nt][half * 2 + 1];
                if (bias) { v0 += bias[col]; v1 += bias[col + 1]; }
                float2 o = make_float2(v0, v1);
                *(float2*)(C + obase + col) = o;
            }
        }
    }
}

// ---------------- GRU elementwise update ----------------
__global__ void k_gru(int t, const float* __restrict__ bxr, const float* __restrict__ bhr,
                      const float* __restrict__ bxz, const float* __restrict__ bhz,
                      const float* __restrict__ bxn, const float* __restrict__ bhn) {
    size_t idx = (size_t)blockIdx.x * blockDim.x + threadIdx.x;
    const size_t total = (size_t)MROWS * HIDD;
    if (idx >= total) return;
    int j = (int)(idx & 255);
    size_t row = idx >> 8;
    const float* gx = g_Gx + ((size_t)t * MROWS + row) * G3;
    const float* gh = g_Gh + row * G3;
    float r = 1.0f / (1.0f + expf(-(gx[j] + bxr[j] + gh[j] + bhr[j])));
    float z = 1.0f / (1.0f + expf(-(gx[256 + j] + bxz[j] + gh[256 + j] + bhz[j])));
    float n = tanhf(gx[512 + j] + bxn[j] + r * (gh[512 + j] + bhn[j]));
    float hv = g_h[idx];
    float hn = (1.0f - z) * hv + z * n;
    g_h[idx] = hn;
    split2(hn, &g_hh[idx], &g_hl[idx]);
}

// ---------------- launch ----------------
extern "C" void kernel_launch(void* const* d_in, const int* in_sizes, int n_in,
                              void* d_out, int out_size) {
    const float* x    = (const float*)d_in[0];
    const int*   ei   = (const int*)d_in[1];
    const float* W_xr = (const float*)d_in[2];  const float* b_xr = (const float*)d_in[3];
    const float* W_hr = (const float*)d_in[4];  const float* b_hr = (const float*)d_in[5];
    const float* W_xz = (const float*)d_in[6];  const float* b_xz = (const float*)d_in[7];
    const float* W_hz = (const float*)d_in[8];  const float* b_hz = (const float*)d_in[9];
    const float* W_xn = (const float*)d_in[10]; const float* b_xn = (const float*)d_in[11];
    const float* W_hn = (const float*)d_in[12]; const float* b_hn = (const float*)d_in[13];
    const float* W_fc = (const float*)d_in[14]; const float* b_fc = (const float*)d_in[15];
    float* outp = (float*)d_out;
    const int* src = ei;
    const int* dst = ei + NE;

    // idempotent config; executed on first (uncaptured) correctness call
    static bool attr_set = false;
    if (!attr_set) {
        cudaFuncSetAttribute(k_mma, cudaFuncAttributeMaxDynamicSharedMemorySize, SMEMB);
        attr_set = true;
    }

    __nv_bfloat16 *p_xh, *p_xl, *p_agh, *p_agl, *p_hh, *p_hl;
    __nv_bfloat16 *p_Wxh, *p_Wxl, *p_Whh, *p_Whl, *p_Wfh, *p_Wfl;
    float *p_Gx, *p_Gh;
    cudaGetSymbolAddress((void**)&p_xh,  g_xh);  cudaGetSymbolAddress((void**)&p_xl,  g_xl);
    cudaGetSymbolAddress((void**)&p_agh, g_agh); cudaGetSymbolAddress((void**)&p_agl, g_agl);
    cudaGetSymbolAddress((void**)&p_hh,  g_hh);  cudaGetSymbolAddress((void**)&p_hl,  g_hl);
    cudaGetSymbolAddress((void**)&p_Wxh, g_Wxh); cudaGetSymbolAddress((void**)&p_Wxl, g_Wxl);
    cudaGetSymbolAddress((void**)&p_Whh, g_Whh); cudaGetSymbolAddress((void**)&p_Whl, g_Whl);
    cudaGetSymbolAddress((void**)&p_Wfh, g_Wfh); cudaGetSymbolAddress((void**)&p_Wfl, g_Wfl);
    cudaGetSymbolAddress((void**)&p_Gx,  g_Gx);  cudaGetSymbolAddress((void**)&p_Gh,  g_Gh);

    // my0: fused weight prep + h zero
    k_prep<<<(int)((PR_TOTAL + 255) / 256), 256>>>(W_xr, W_xz, W_xn, W_hr, W_hz, W_hn, W_fc);
    // my1: whole graph build in one single-block kernel
    k_graph<<<1, 1024>>>(src, dst);
    // my2: x aggregation for all (b,t), reordered to [t][b][N][IND]
    k_aggx<<<dim3(NNODES, NB * TT), IND>>>(x);
    // my3 (global #5 -> ncu capture target): Gx for ALL timesteps in one GEMM
    k_mma<<<dim3(G3 / 128, (int)(MX / 128)), 256, SMEMB>>>(
        p_xh, p_xl, p_Wxh, p_Wxl, p_Gx, (long)MX, IND, nullptr, 0, 0);

    const int MT = (MROWS + 127) / 128;  // 157
    for (int t = 0; t < TT; t++) {
        k_aggh<<<dim3(NNODES, NB), HIDD>>>();
        k_mma<<<dim3(G3 / 128, MT), 256, SMEMB>>>(
            p_agh, p_agl, p_Whh, p_Whl, p_Gh, (long)MROWS, HIDD, nullptr, 0, 0);
        k_gru<<<((size_t)MROWS * HIDD + 255) / 256, 256>>>(t, b_xr, b_hr, b_xz, b_hz, b_xn, b_hn);
        k_mma<<<dim3(OUTD / 128, MT), 256, SMEMB>>>(
            p_hh, p_hl, p_Wfh, p_Wfl, outp, (long)MROWS, HIDD, b_fc, 1, t);
    }
}